// round 17
// baseline (speedup 1.0000x reference)
#include <cuda_runtime.h>
#include <cuda_bf16.h>
#include <math.h>
#include <cstdint>

#define BB 2
#define TT 2048
#define CC 2048
#define HH 16
#define DD 128
#define MM (BB*TT)
#define NQKV (3*CC)

// ---------------- scratch (__device__ globals; NEVER passed as host-side kernel args) ----------------
static __device__ __align__(256) float g_cos[TT*(DD/2)];
static __device__ __align__(256) float g_sin[TT*(DD/2)];
static __device__ __align__(256) __nv_bfloat16 g_AOh[(size_t)MM*CC],   g_AOl[(size_t)MM*CC];
static __device__ __align__(256) __nv_bfloat16 g_Qh[(size_t)BB*HH*TT*DD], g_Ql[(size_t)BB*HH*TT*DD];
static __device__ __align__(256) __nv_bfloat16 g_Kh[(size_t)BB*HH*TT*DD], g_Kl[(size_t)BB*HH*TT*DD];
static __device__ __align__(256) __nv_bfloat16 g_Vh[(size_t)BB*HH*TT*DD], g_Vl[(size_t)BB*HH*TT*DD];
static __device__ __align__(256) __nv_bfloat16 g_Vth[(size_t)BB*HH*TT*DD], g_Vtl[(size_t)BB*HH*TT*DD];
// int8 planes, k-chunk-outer: plane[(k>>5)*ROWS*32 + row*32 + (k&31)]
static __device__ __align__(256) signed char g_A0x [(size_t)MM*CC],  g_A1x [(size_t)MM*CC];
static __device__ __align__(256) signed char g_A0ao[(size_t)MM*CC],  g_A1ao[(size_t)MM*CC];
static __device__ __align__(256) signed char g_B0q[(size_t)NQKV*CC], g_B1q[(size_t)NQKV*CC];
static __device__ __align__(256) signed char g_B0p[(size_t)CC*CC],   g_B1p[(size_t)CC*CC];
static __device__ __align__(256) float g_sX[MM], g_sAO[MM], g_sWq[NQKV], g_sWp[CC];
static __device__ unsigned g_mWq_u[NQKV], g_mWp_u[CC];

__device__ __forceinline__ void mma16816(float* c, const uint32_t* a, const uint32_t* b){
    asm volatile("mma.sync.aligned.m16n8k16.row.col.f32.bf16.bf16.f32 "
                 "{%0,%1,%2,%3}, {%4,%5,%6,%7}, {%8,%9}, {%0,%1,%2,%3};"
                 : "+f"(c[0]), "+f"(c[1]), "+f"(c[2]), "+f"(c[3])
                 : "r"(a[0]), "r"(a[1]), "r"(a[2]), "r"(a[3]), "r"(b[0]), "r"(b[1]));
}
__device__ __forceinline__ void imma16832(int* c, const uint32_t* a, const uint32_t* b){
    asm volatile("mma.sync.aligned.m16n8k32.row.col.s32.s8.s8.s32 "
                 "{%0,%1,%2,%3}, {%4,%5,%6,%7}, {%8,%9}, {%0,%1,%2,%3};"
                 : "+r"(c[0]), "+r"(c[1]), "+r"(c[2]), "+r"(c[3])
                 : "r"(a[0]), "r"(a[1]), "r"(a[2]), "r"(a[3]), "r"(b[0]), "r"(b[1]));
}
__device__ __forceinline__ void ldx4(uint32_t* r, uint32_t addr){
    asm volatile("ldmatrix.sync.aligned.m8n8.x4.shared.b16 {%0,%1,%2,%3}, [%4];"
                 : "=r"(r[0]), "=r"(r[1]), "=r"(r[2]), "=r"(r[3]) : "r"(addr));
}
__device__ __forceinline__ uint32_t pack2(__nv_bfloat16 a, __nv_bfloat16 b){
    return ((uint32_t)*(uint16_t*)&b << 16) | *(uint16_t*)&a;
}
__device__ __forceinline__ uint32_t smem_u32(const void* p){
    uint32_t a;
    asm("{ .reg .u64 t; cvta.to.shared.u64 t, %1; cvt.u32.u64 %0, t; }" : "=r"(a) : "l"(p));
    return a;
}
__device__ __forceinline__ void cp16(uint32_t dst, const void* src){
    asm volatile("cp.async.cg.shared.global [%0], [%1], 16;" :: "r"(dst), "l"(src));
}

// ---------------- init ----------------
__global__ void rope_init_kernel() {
    int idx = blockIdx.x * blockDim.x + threadIdx.x;
    if (idx >= TT*(DD/2)) return;
    int t = idx / (DD/2);
    int i = idx - t*(DD/2);
    float inv = powf(10000.0f, -(float)(2*i) / (float)DD);
    float ang = (float)t * inv;
    g_cos[idx] = cosf(ang);
    g_sin[idx] = sinf(ang);
}

// ---------------- per-row two-level quant: SEL0 x -> A0x/A1x/sX ; SEL1 AO -> A0ao/A1ao/sAO ----------------
template<int SEL>
__global__ void quant_rows_kernel(const float* __restrict__ xin) {
    __shared__ float wmax[8];
    __shared__ float smx;
    int m = blockIdx.x, tid = threadIdx.x;
    float v[8];
    if (SEL == 0) {
        float4 f0 = *(const float4*)(xin + (size_t)m*CC + tid*8);
        float4 f1 = *(const float4*)(xin + (size_t)m*CC + tid*8 + 4);
        v[0]=f0.x; v[1]=f0.y; v[2]=f0.z; v[3]=f0.w;
        v[4]=f1.x; v[5]=f1.y; v[6]=f1.z; v[7]=f1.w;
    } else {
        uint4 h = *(const uint4*)(g_AOh + (size_t)m*CC + tid*8);
        uint4 l = *(const uint4*)(g_AOl + (size_t)m*CC + tid*8);
        const uint32_t hw[4] = {h.x,h.y,h.z,h.w}, lw[4] = {l.x,l.y,l.z,l.w};
        #pragma unroll
        for (int j = 0; j < 4; j++) {
            __nv_bfloat162 hh = *(const __nv_bfloat162*)&hw[j];
            __nv_bfloat162 ll = *(const __nv_bfloat162*)&lw[j];
            v[2*j]   = __bfloat162float(hh.x) + __bfloat162float(ll.x);
            v[2*j+1] = __bfloat162float(hh.y) + __bfloat162float(ll.y);
        }
    }
    float mx = 0.f;
    #pragma unroll
    for (int j = 0; j < 8; j++) mx = fmaxf(mx, fabsf(v[j]));
    #pragma unroll
    for (int off = 16; off > 0; off >>= 1)
        mx = fmaxf(mx, __shfl_xor_sync(0xffffffffu, mx, off));
    if ((tid & 31) == 0) wmax[tid >> 5] = mx;
    __syncthreads();
    if (tid == 0) {
        float t = wmax[0];
        #pragma unroll
        for (int j = 1; j < 8; j++) t = fmaxf(t, wmax[j]);
        smx = t;
        ((SEL == 0) ? g_sX : g_sAO)[m] = t / 127.0f;
    }
    __syncthreads();
    float inv = (smx > 0.f) ? 127.0f / smx : 0.f;
    signed char q0[8], q1[8];
    #pragma unroll
    for (int j = 0; j < 8; j++) {
        float xs = v[j] * inv;
        float a0 = rintf(xs);
        float a1 = rintf((xs - a0) * 128.0f);
        q0[j] = (signed char)(int)a0;
        q1[j] = (signed char)(int)a1;
    }
    signed char* p0 = (SEL == 0) ? g_A0x : g_A0ao;
    signed char* p1 = (SEL == 0) ? g_A1x : g_A1ao;
    size_t dst = (size_t)(tid >> 2)*MM*32 + (size_t)m*32 + (tid & 3)*8;
    *(uint2*)(p0 + dst) = *(uint2*)q0;
    *(uint2*)(p1 + dst) = *(uint2*)q1;
}

// ---------------- per-col absmax of W (atomicMax, idempotent across graph replays) ----------------
template<int SEL>
__global__ void absmax_w_kernel(const float* __restrict__ W) {
    constexpr int N = (SEL == 0) ? NQKV : CC;
    unsigned* dst = (SEL == 0) ? g_mWq_u : g_mWp_u;
    __shared__ unsigned sm[32];
    int k0 = blockIdx.y * 32, n0 = blockIdx.x * 32;
    int tid = threadIdx.x;
    if (tid < 32) sm[tid] = 0;
    __syncthreads();
    int nn = tid & 31;
    unsigned loc = 0;
    #pragma unroll
    for (int r = 0; r < 4; r++) {
        int kk = (tid >> 5) + r*8;
        loc = max(loc, __float_as_uint(fabsf(W[(size_t)(k0+kk)*N + n0 + nn])));
    }
    atomicMax(&sm[nn], loc);
    __syncthreads();
    if (tid < 32) atomicMax(&dst[n0 + tid], sm[tid]);
}

// ---------------- W transpose + two-level quant into k-chunk-outer planes ----------------
template<int SEL>
__global__ void quant_wT_kernel(const float* __restrict__ W) {
    constexpr int N = (SEL == 0) ? NQKV : CC;
    const unsigned* mArr = (SEL == 0) ? g_mWq_u : g_mWp_u;
    float* sArr = (SEL == 0) ? g_sWq : g_sWp;
    signed char* p0 = (SEL == 0) ? g_B0q : g_B0p;
    signed char* p1 = (SEL == 0) ? g_B1q : g_B1p;
    __shared__ float t[32][33];
    int k0 = blockIdx.y * 32, n0 = blockIdx.x * 32;
    int tid = threadIdx.x;
    #pragma unroll
    for (int r = 0; r < 4; r++) {
        int kk = (tid >> 5) + r*8, nn = tid & 31;
        t[kk][nn] = W[(size_t)(k0+kk)*N + n0 + nn];
    }
    __syncthreads();
    int nn = tid >> 3, ks = (tid & 7) * 4;
    int n = n0 + nn;
    float mx = __uint_as_float(mArr[n]);
    float inv = (mx > 0.f) ? 127.0f / mx : 0.f;
    if (k0 == 0 && (tid & 7) == 0) sArr[n] = mx / 127.0f;
    signed char q0[4], q1[4];
    #pragma unroll
    for (int j = 0; j < 4; j++) {
        float xs = t[ks+j][nn] * inv;
        float a0 = rintf(xs);
        float a1 = rintf((xs - a0) * 128.0f);
        q0[j] = (signed char)(int)a0;
        q1[j] = (signed char)(int)a1;
    }
    size_t dst = (size_t)(k0 >> 5)*N*32 + (size_t)n*32 + ks;
    *(uint32_t*)(p0 + dst) = *(uint32_t*)q0;
    *(uint32_t*)(p1 + dst) = *(uint32_t*)q1;
}

// ---------------- int8 IMMA GEMM: CTA 128x128, warp 32x64, 3-stage cp.async ring ----------------
#define IPLANE 6144               // 128 rows * 48B padded
#define ISTG   (4*IPLANE)
#define IMMA_SMEM (3*ISTG)        // 73728

template<int PHASE>
__global__ __launch_bounds__(256, 1)
void gemm_imma(const float* __restrict__ bias, float* __restrict__ out_p)
{
    constexpr int Ntot = (PHASE == 0) ? NQKV : CC;
    const signed char* __restrict__ pA0 = (PHASE == 0) ? g_A0x : g_A0ao;
    const signed char* __restrict__ pA1 = (PHASE == 0) ? g_A1x : g_A1ao;
    const signed char* __restrict__ pB0 = (PHASE == 0) ? g_B0q : g_B0p;
    const signed char* __restrict__ pB1 = (PHASE == 0) ? g_B1q : g_B1p;
    const float* __restrict__ sA = (PHASE == 0) ? g_sX  : g_sAO;
    const float* __restrict__ sB = (PHASE == 0) ? g_sWq : g_sWp;

    extern __shared__ char smraw[];
    const uint32_t sb = smem_u32(smraw);
    const int tid  = threadIdx.x;
    const int lane = tid & 31;
    const int wid  = tid >> 5;
    const int wm   = wid & 3;
    const int wn   = wid >> 2;

    const int nT = Ntot / 128;
    int id  = blockIdx.x;
    int gsz = 8 * nT;
    int bm  = (id / gsz) * 8 + (id % gsz) % 8;
    int bn  = (id % gsz) / 8;
    const int m0 = bm * 128, n0 = bn * 128;

    const int row = tid >> 1, half = tid & 1;
    auto issue_stage = [&](int s) {
        uint32_t base = sb + (uint32_t)(s % 3)*ISTG + row*48 + half*16;
        size_t ac = (size_t)s*MM*32   + (size_t)(m0 + row)*32 + half*16;
        size_t bc = (size_t)s*Ntot*32 + (size_t)(n0 + row)*32 + half*16;
        cp16(base,            pA0 + ac);
        cp16(base +   IPLANE, pA1 + ac);
        cp16(base + 2*IPLANE, pB0 + bc);
        cp16(base + 3*IPLANE, pB1 + bc);
        asm volatile("cp.async.commit_group;");
    };

    int accM[2][8][4], accD[2][8][4];
    #pragma unroll
    for (int mt = 0; mt < 2; mt++)
        #pragma unroll
        for (int nt = 0; nt < 8; nt++)
            #pragma unroll
            for (int q = 0; q < 4; q++) { accM[mt][nt][q] = 0; accD[mt][nt][q] = 0; }

    const uint32_t aOff = (uint32_t)((wm*32 + (lane & 15))*48 + (lane >> 4)*16);
    const uint32_t bOff = (uint32_t)((wn*64 + (lane >> 4)*8 + (lane & 7))*48 + ((lane >> 3) & 1)*16);

    const int NS = CC / 32;   // 64
    issue_stage(0);
    issue_stage(1);
    for (int s = 0; s < NS; s++) {
        asm volatile("cp.async.wait_group 1;" ::: "memory");
        __syncthreads();
        if (s + 2 < NS) issue_stage(s + 2);

        const uint32_t base = sb + (uint32_t)(s % 3)*ISTG;
        uint32_t a0f[2][4], a1f[2][4];
        #pragma unroll
        for (int mt = 0; mt < 2; mt++) {
            uint32_t aa = base + aOff + mt*16*48;
            ldx4(a0f[mt], aa);
            ldx4(a1f[mt], aa + IPLANE);
        }
        #pragma unroll
        for (int np = 0; np < 4; np++) {   // B level 0: M += a0*b0, D += a1*b0
            uint32_t r[4];
            ldx4(r, base + 2*IPLANE + bOff + np*16*48);
            uint32_t b0[2] = { r[0], r[1] }, b1[2] = { r[2], r[3] };
            #pragma unroll
            for (int mt = 0; mt < 2; mt++) {
                imma16832(accM[mt][2*np],   a0f[mt], b0);
                imma16832(accD[mt][2*np],   a1f[mt], b0);
                imma16832(accM[mt][2*np+1], a0f[mt], b1);
                imma16832(accD[mt][2*np+1], a1f[mt], b1);
            }
        }
        #pragma unroll
        for (int np = 0; np < 4; np++) {   // B level 1: D += a0*b1
            uint32_t r[4];
            ldx4(r, base + 3*IPLANE + bOff + np*16*48);
            uint32_t b0[2] = { r[0], r[1] }, b1[2] = { r[2], r[3] };
            #pragma unroll
            for (int mt = 0; mt < 2; mt++) {
                imma16832(accD[mt][2*np],   a0f[mt], b0);
                imma16832(accD[mt][2*np+1], a0f[mt], b1);
            }
        }
    }

    const int gid = lane >> 2, tig = lane & 3;
    #pragma unroll
    for (int mt = 0; mt < 2; mt++) {
        int m = m0 + wm*32 + mt*16 + gid;
        float sa0 = sA[m], sa1 = sA[m+8];
        int bi = m >> 11;
        int t0 = m & 2047, t1 = t0 + 8;
        #pragma unroll
        for (int nt = 0; nt < 8; nt++) {
            int n = n0 + wn*64 + nt*8 + tig*2;     // even
            float sb0 = sB[n], sb1 = sB[n+1];
            float bv0 = bias[n], bv1 = bias[n+1];
            float c0 = ((float)accM[mt][nt][0] + (float)accD[mt][nt][0]*0.0078125f) * (sa0*sb0) + bv0;
            float c1 = ((float)accM[mt][nt][1] + (float)accD[mt][nt][1]*0.0078125f) * (sa0*sb1) + bv1;
            float c2 = ((float)accM[mt][nt][2] + (float)accD[mt][nt][2]*0.0078125f) * (sa1*sb0) + bv0;
            float c3 = ((float)accM[mt][nt][3] + (float)accD[mt][nt][3]*0.0078125f) * (sa1*sb1) + bv1;
            if (PHASE == 1) {
                float* out = out_p;
                *(float2*)(out + (size_t)m*Ntot + n)     = make_float2(c0, c1);
                *(float2*)(out + (size_t)(m+8)*Ntot + n) = make_float2(c2, c3);
            } else {
                int which = n / CC;
                int w2 = n - which*CC;
                int h = w2 >> 7, d = w2 & 127;      // d even
                if (which != 2) {
                    float cs0 = g_cos[t0*64 + (d >> 1)], sn0 = g_sin[t0*64 + (d >> 1)];
                    float cs1 = g_cos[t1*64 + (d >> 1)], sn1 = g_sin[t1*64 + (d >> 1)];
                    float a0 = c0, a1 = c1; c0 = a0*cs0 - a1*sn0; c1 = a0*sn0 + a1*cs0;
                    float a2 = c2, a3 = c3; c2 = a2*cs1 - a3*sn1; c3 = a2*sn1 + a3*cs1;
                }
                __nv_bfloat16* ph = (which == 0) ? g_Qh : (which == 1) ? g_Kh : g_Vh;
                __nv_bfloat16* pl = (which == 0) ? g_Ql : (which == 1) ? g_Kl : g_Vl;
                size_t off0 = ((size_t)(bi*HH + h)*TT + t0)*DD + d;
                size_t off1 = off0 + (size_t)8*DD;
                __nv_bfloat16 h0 = __float2bfloat16(c0), h1 = __float2bfloat16(c1);
                __nv_bfloat16 h2 = __float2bfloat16(c2), h3 = __float2bfloat16(c3);
                *(__nv_bfloat162*)(ph + off0) = __halves2bfloat162(h0, h1);
                *(__nv_bfloat162*)(ph + off1) = __halves2bfloat162(h2, h3);
                *(__nv_bfloat162*)(pl + off0) = __halves2bfloat162(
                    __float2bfloat16(c0 - __bfloat162float(h0)), __float2bfloat16(c1 - __bfloat162float(h1)));
                *(__nv_bfloat162*)(pl + off1) = __halves2bfloat162(
                    __float2bfloat16(c2 - __bfloat162float(h2)), __float2bfloat16(c3 - __bfloat162float(h3)));
            }
        }
    }
}

// ---------------- V transpose (verified) ----------------
__global__ void transpose_v_kernel() {
    __shared__ __nv_bfloat16 th[64][66], tl[64][66];
    int bh = blockIdx.y;
    int t0 = (blockIdx.x & 31) * 64;
    int d0 = (blockIdx.x >> 5) * 64;
    const __nv_bfloat16* Vh = g_Vh + (size_t)bh*TT*DD;
    const __nv_bfloat16* Vl = g_Vl + (size_t)bh*TT*DD;
    int tid = threadIdx.x;
    #pragma unroll
    for (int p = 0; p < 8; p++) {
        int idx = tid + p*256;
        int r = idx >> 5, c = (idx & 31) * 2;
        *(uint32_t*)&th[r][c] = *(const uint32_t*)(Vh + (size_t)(t0+r)*DD + d0 + c);
        *(uint32_t*)&tl[r][c] = *(const uint32_t*)(Vl + (size_t)(t0+r)*DD + d0 + c);
    }
    __syncthreads();
    __nv_bfloat16* Oth = g_Vth + (size_t)bh*DD*TT;
    __nv_bfloat16* Otl = g_Vtl + (size_t)bh*DD*TT;
    #pragma unroll
    for (int p = 0; p < 8; p++) {
        int idx = tid + p*256;
        int d = idx >> 5, t = (idx & 31) * 2;
        *(uint32_t*)(Oth + (size_t)(d0+d)*TT + t0 + t) = pack2(th[t][d], th[t+1][d]);
        *(uint32_t*)(Otl + (size_t)(d0+d)*TT + t0 + t) = pack2(tl[t][d], tl[t+1][d]);
    }
}

// ---------------- mma.sync flash attention (verified R15, unchanged) ----------------
#define AQ_STR 272
#define AV_STR 144
#define SM_QH 0
#define SM_QL 34816
#define A_KBUF 34816
#define A_VBUF 36864
#define SM_K0 69632
#define SM_V0 (SM_K0 + 2*A_KBUF)
#define ATTN_SMEM (SM_V0 + 2*A_VBUF)

__global__ __launch_bounds__(256, 1) void attn_mma_kernel() {
    extern __shared__ char smc[];
    const uint32_t sb = smem_u32(smc);
    const int tid  = threadIdx.x;
    const int lane = tid & 31;
    const int w    = tid >> 5;
    const int r1   = lane >> 2;
    const int c4   = lane & 3;
    const int bh   = blockIdx.y;
    const int q0   = (int)(gridDim.x - 1 - blockIdx.x) * 128;

    const __nv_bfloat16* Qh = g_Qh + (size_t)bh*TT*DD;
    const __nv_bfloat16* Ql = g_Ql + (size_t)bh*TT*DD;
    const __nv_bfloat16* Kh = g_Kh + (size_t)bh*TT*DD;
    const __nv_bfloat16* Kl = g_Kl + (size_t)bh*TT*DD;
    const __nv_bfloat16* Vth = g_Vth + (size_t)bh*DD*TT;
    const __nv_bfloat16* Vtl = g_Vtl + (size_t)bh*DD*TT;

    auto issue_kv = [&](int kt, int b) {
        uint32_t kb = sb + SM_K0 + (uint32_t)b*A_KBUF;
        uint32_t vb = sb + SM_V0 + (uint32_t)b*A_VBUF;
        #pragma unroll
        for (int p = 0; p < 4; p++) {
            int c = tid + p*256;
            int row = c >> 4, c16 = c & 15;
            cp16(kb +         row*AQ_STR + c16*16, Kh + (size_t)(kt*64+row)*DD + c16*8);
            cp16(kb + 17408 + row*AQ_STR + c16*16, Kl + (size_t)(kt*64+row)*DD + c16*8);
        }
        #pragma unroll
        for (int p = 0; p < 4; p++) {
            int c = tid + p*256;
            int row = c >> 3, c8 = c & 7;
            cp16(vb +         row*AV_STR + c8*16, Vth + (size_t)row*TT + kt*64 + c8*8);
            cp16(vb + 18432 + row*AV_STR + c8*16, Vtl + (size_t)row*TT + kt*64 + c8*8);
        }
        asm volatile("cp.async.commit_group;");
    };

    issue_kv(0, 0);

    #pragma unroll
    for (int p = 0; p < 8; p++) {
        int idx = tid + p*256;
        int row = idx >> 4, c16 = idx & 15;
        *(float4*)(smc + SM_QH + row*AQ_STR + c16*16) = *(const float4*)(Qh + (size_t)(q0+row)*DD + c16*8);
        *(float4*)(smc + SM_QL + row*AQ_STR + c16*16) = *(const float4*)(Ql + (size_t)(q0+row)*DD + c16*8);
    }

    const int qrow1 = q0 + w*16 + r1;
    const int qrow2 = qrow1 + 8;
    float m1 = -1e30f, m2 = -1e30f, l1 = 0.f, l2 = 0.f;
    float O[16][4];
    #pragma unroll
    for (int vt = 0; vt < 16; vt++)
        #pragma unroll
        for (int q = 0; q < 4; q++) O[vt][q] = 0.f;

    const float scale = 0.08838834764831845f;
    const int ktmax = q0/64 + 1;

    const uint32_t aOffQ = (uint32_t)((w*16 + (lane & 15))*AQ_STR + (lane >> 4)*16);
    const uint32_t bOffK = (uint32_t)(((lane >> 4)*8 + (lane & 7))*AQ_STR + ((lane >> 3) & 1)*16);
    const uint32_t bOffV = (uint32_t)(((lane >> 4)*8 + (lane & 7))*AV_STR + ((lane >> 3) & 1)*16);

    for (int kt = 0; kt <= ktmax; kt++) {
        asm volatile("cp.async.wait_group 0;" ::: "memory");
        __syncthreads();
        if (kt + 1 <= ktmax) issue_kv(kt + 1, (kt + 1) & 1);

        const uint32_t kbH = sb + SM_K0 + (uint32_t)(kt & 1)*A_KBUF;
        const uint32_t vbH = sb + SM_V0 + (uint32_t)(kt & 1)*A_VBUF;

        float S[8][4];
        #pragma unroll
        for (int nt = 0; nt < 8; nt++)
            #pragma unroll
            for (int q = 0; q < 4; q++) S[nt][q] = 0.f;
        #pragma unroll
        for (int kc = 0; kc < 8; kc++) {
            uint32_t ah[4], al[4];
            uint32_t aa = sb + SM_QH + aOffQ + kc*32;
            ldx4(ah, aa);
            ldx4(al, aa + (SM_QL - SM_QH));
            #pragma unroll
            for (int np = 0; np < 4; np++) {
                uint32_t ka = kbH + bOffK + np*16*AQ_STR + kc*32;
                uint32_t rh[4], rl[4];
                ldx4(rh, ka);
                ldx4(rl, ka + 17408);
                uint32_t bh0[2] = { rh[0], rh[1] }, bh1[2] = { rh[2], rh[3] };
                uint32_t bl0[2] = { rl[0], rl[1] }, bl1[2] = { rl[2], rl[3] };
                mma16816(S[2*np],   ah, bh0);
                mma16816(S[2*np],   ah, bl0);
                mma16816(S[2*np],   al, bh0);
                mma16816(S[2*np+1], ah, bh1);
                mma16816(S[2*np+1], ah, bl1);
                mma16816(S[2*np+1], al, bh1);
            }
        }

        float mx1 = -1e30f, mx2 = -1e30f;
        #pragma unroll
        for (int nt = 0; nt < 8; nt++) {
            int col0 = kt*64 + nt*8 + 2*c4;
            S[nt][0] = (col0     <= qrow1) ? S[nt][0]*scale : -1e30f;
            S[nt][1] = (col0 + 1 <= qrow1) ? S[nt][1]*scale : -1e30f;
            S[nt][2] = (col0     <= qrow2) ? S[nt][2]*scale : -1e30f;
            S[nt][3] = (col0 + 1 <= qrow2) ? S[nt][3]*scale : -1e30f;
            mx1 = fmaxf(mx1, fmaxf(S[nt][0], S[nt][1]));
            mx2 = fmaxf(mx2, fmaxf(S[nt][2], S[nt][3]));
        }
        #pragma unroll
        for (int off = 1; off <= 2; off <<= 1) {
            mx1 = fmaxf(mx1, __shfl_xor_sync(0xffffffffu, mx1, off));
            mx2 = fmaxf(mx2, __shfl_xor_sync(0xffffffffu, mx2, off));
        }
        float mn1 = fmaxf(m1, mx1), mn2 = fmaxf(m2, mx2);
        float al1 = __expf(m1 - mn1), al2 = __expf(m2 - mn2);
        m1 = mn1; m2 = mn2;

        uint32_t ph1[8], ph2[8], pl1[8], pl2[8];
        float rs1 = 0.f, rs2 = 0.f;
        #pragma unroll
        for (int nt = 0; nt < 8; nt++) {
            float p00 = __expf(S[nt][0] - mn1), p01 = __expf(S[nt][1] - mn1);
            float p10 = __expf(S[nt][2] - mn2), p11 = __expf(S[nt][3] - mn2);
            rs1 += p00 + p01; rs2 += p10 + p11;
            __nv_bfloat16 h00 = __float2bfloat16(p00), h01 = __float2bfloat16(p01);
            __nv_bfloat16 h10 = __float2bfloat16(p10), h11 = __float2bfloat16(p11);
            ph1[nt] = pack2(h00, h01);
            ph2[nt] = pack2(h10, h11);
            pl1[nt] = pack2(__float2bfloat16(p00 - __bfloat162float(h00)),
                            __float2bfloat16(p01 - __bfloat162float(h01)));
            pl2[nt] = pack2(__float2bfloat16(p10 - __bfloat162float(h10)),
                            __float2bfloat16(p11 - __bfloat162float(h11)));
        }
        #pragma unroll
        for (int off = 1; off <= 2; off <<= 1) {
            rs1 += __shfl_xor_sync(0xffffffffu, rs1, off);
            rs2 += __shfl_xor_sync(0xffffffffu, rs2, off);
        }
        l1 = l1*al1 + rs1;
        l2 = l2*al2 + rs2;
        #pragma unroll
        for (int vt = 0; vt < 16; vt++) {
            O[vt][0] *= al1; O[vt][1] *= al1;
            O[vt][2] *= al2; O[vt][3] *= al2;
        }

        #pragma unroll
        for (int kc = 0; kc < 4; kc++) {
            uint32_t pa[4] = { ph1[2*kc], ph2[2*kc], ph1[2*kc+1], ph2[2*kc+1] };
            uint32_t pb[4] = { pl1[2*kc], pl2[2*kc], pl1[2*kc+1], pl2[2*kc+1] };
            #pragma unroll
            for (int vp = 0; vp < 8; vp++) {
                uint32_t va = vbH + bOffV + vp*16*AV_STR + kc*32;
                uint32_t rh[4], rl[4];
                ldx4(rh, va);
                ldx4(rl, va + 18432);
                uint32_t bh0[2] = { rh[0], rh[1] }, bh1[2] = { rh[2], rh[3] };
                uint32_t bl0[2] = { rl[0], rl[1] }, bl1[2] = { rl[2], rl[3] };
                mma16816(O[2*vp],   pa, bh0);
                mma16816(O[2*vp],   pa, bl0);
                mma16816(O[2*vp],   pb, bh0);
                mma16816(O[2*vp+1], pa, bh1);
                mma16816(O[2*vp+1], pa, bl1);
                mma16816(O[2*vp+1], pb, bh1);
            }
        }
    }

    const int b = bh >> 4, h = bh & 15;
    const float i1 = 1.0f / l1, i2 = 1.0f / l2;
    const size_t mrow1 = (size_t)(b*TT + qrow1) * CC;
    const size_t mrow2 = (size_t)(b*TT + qrow2) * CC;
    #pragma unroll
    for (int vt = 0; vt < 16; vt++) {
        int col = h*DD + vt*8 + 2*c4;
        float o00 = O[vt][0]*i1, o01 = O[vt][1]*i1;
        float o10 = O[vt][2]*i2, o11 = O[vt][3]*i2;
        __nv_bfloat16 h00 = __float2bfloat16(o00), h01 = __float2bfloat16(o01);
        __nv_bfloat16 h10 = __float2bfloat16(o10), h11 = __float2bfloat16(o11);
        *(__nv_bfloat162*)(g_AOh + mrow1 + col) = __halves2bfloat162(h00, h01);
        *(__nv_bfloat162*)(g_AOh + mrow2 + col) = __halves2bfloat162(h10, h11);
        *(__nv_bfloat162*)(g_AOl + mrow1 + col) = __halves2bfloat162(
            __float2bfloat16(o00 - __bfloat162float(h00)), __float2bfloat16(o01 - __bfloat162float(h01)));
        *(__nv_bfloat162*)(g_AOl + mrow2 + col) = __halves2bfloat162(
            __float2bfloat16(o10 - __bfloat162float(h10)), __float2bfloat16(o11 - __bfloat162float(h11)));
    }
}

// ---------------- launcher (no __device__ symbols as host-side args) ----------------
extern "C" void kernel_launch(void* const* d_in, const int* in_sizes, int n_in,
                              void* d_out, int out_size) {
    const float* x      = (const float*)d_in[0];
    const float* W_attn = (const float*)d_in[1];
    const float* b_attn = (const float*)d_in[2];
    const float* W_proj = (const float*)d_in[3];
    const float* b_proj = (const float*)d_in[4];
    float* out = (float*)d_out;

    cudaFuncSetAttribute(gemm_imma<0>, cudaFuncAttributeMaxDynamicSharedMemorySize, IMMA_SMEM);
    cudaFuncSetAttribute(gemm_imma<1>, cudaFuncAttributeMaxDynamicSharedMemorySize, IMMA_SMEM);
    cudaFuncSetAttribute(attn_mma_kernel, cudaFuncAttributeMaxDynamicSharedMemorySize, ATTN_SMEM);

    rope_init_kernel<<<(TT*(DD/2) + 255)/256, 256>>>();
    quant_rows_kernel<0><<<MM, 256>>>(x);
    absmax_w_kernel<0><<<dim3(NQKV/32, CC/32), 256>>>(W_attn);
    absmax_w_kernel<1><<<dim3(CC/32, CC/32), 256>>>(W_proj);
    quant_wT_kernel<0><<<dim3(NQKV/32, CC/32), 256>>>(W_attn);
    quant_wT_kernel<1><<<dim3(CC/32, CC/32), 256>>>(W_proj);

    gemm_imma<0><<<(MM/128)*(NQKV/128), 256, IMMA_SMEM>>>(b_attn, nullptr);

    transpose_v_kernel<<<dim3(64, BB*HH), 256>>>();

    attn_mma_kernel<<<dim3(TT/128, BB*HH), 256, ATTN_SMEM>>>();

    quant_rows_kernel<1><<<MM, 256>>>(x);

    gemm_imma<1><<<(MM/128)*(CC/128), 256, IMMA_SMEM>>>(b_proj, out);
}